// round 4
// baseline (speedup 1.0000x reference)
#include <cuda_runtime.h>
#include <math.h>

typedef unsigned long long ull;

// Problem constants
#define BATCH   8
#define SEQ     2048
#define DMODEL  1024
#define DSPACE  64
#define N_QK    512
#define N_V     256
#define N_REL   128
#define N_VAL   32
#define N_TOT   928
#define K_QK    64
#define K_V     32
#define K_REL   16
#define K_VAL   3

#define TPB      128
#define NTHREADS 256
#define NBLOCKS  (BATCH * SEQ / TPB)      // 128, 16 per batch

// Output layout (float32, reference return order)
#define OFF_IDXQK 0
#define OFF_IDXV  (OFF_IDXQK + BATCH*K_QK)
#define OFF_RWQ   (OFF_IDXV  + BATCH*K_V)
#define OFF_RWK   (OFF_RWQ   + BATCH*N_REL)
#define OFF_VW    (OFF_RWK   + BATCH*N_REL)
#define OFF_WQK   (OFF_VW    + BATCH*N_VAL)
#define OFF_WV    (OFF_WQK   + BATCH*N_QK)

// Shared memory byte offsets
#define SM_HSP   131072     // HsP: ull[64][66] = 33792
#define SM_WL    164864     // w_local float[928]
#define SM_IMP   168576     // impS float[128]
#define SM_PART  169088     // partS float[256]
#define SM_ALPHA 170112     // alphaS float[128]
#define SM_WPART 170624     // wpart float[2048] = 8192
#define SMEM_BYTES 178816

#define XSP_STRIDE 130
#define HSP_STRIDE 66

// device scratch (no allocation allowed)
__device__ float g_embT[DSPACE * N_TOT];        // normalized emb transposed [d][n]
__device__ float g_wpart[NBLOCKS][N_TOT];       // per-block partial w
__device__ int   g_cnt[BATCH];                  // completion counters

// ---------------- f32x2 helpers ----------------
__device__ __forceinline__ ull d_pack(float x, float y) {
    ull r; asm("mov.b64 %0, {%1, %2};" : "=l"(r) : "f"(x), "f"(y)); return r;
}
__device__ __forceinline__ ull d_dup(float x) {
    ull r; asm("mov.b64 %0, {%1, %1};" : "=l"(r) : "f"(x)); return r;
}
__device__ __forceinline__ void d_unpack(ull v, float& x, float& y) {
    asm("mov.b64 {%0, %1}, %2;" : "=f"(x), "=f"(y) : "l"(v));
}
__device__ __forceinline__ ull d_fma2(ull a, ull b, ull c) {
    ull d; asm("fma.rn.f32x2 %0, %1, %2, %3;" : "=l"(d) : "l"(a), "l"(b), "l"(c)); return d;
}
__device__ __forceinline__ ull d_add2(ull a, ull b) {
    ull d; asm("add.rn.f32x2 %0, %1, %2;" : "=l"(d) : "l"(a), "l"(b)); return d;
}

// ---------------- prep: normalize emb (transposed) + reset counters ----------------
__global__ void prep_kernel(const float* __restrict__ emb) {
    int r = blockIdx.x;     // neuron 0..927
    int t = threadIdx.x;    // dim 0..63
    if (r == 0 && t < BATCH) g_cnt[t] = 0;
    __shared__ float s[64];
    float v = emb[r * DSPACE + t];
    s[t] = v * v;
    __syncthreads();
    #pragma unroll
    for (int o = 32; o > 0; o >>= 1) {
        if (t < o) s[t] += s[t + o];
        __syncthreads();
    }
    float norm = sqrtf(s[0]);
    g_embT[t * N_TOT + r] = v / norm;
}

// ---------------- GEMM2 + softmax + routed-weight slice ----------------
template<int N, int LO>
__device__ __forceinline__ void do_slice(char* sm, int tid) {
    float* embS   = (float*)sm;
    ull*   HsP    = (ull*)(sm + SM_HSP);
    float* w_local= (float*)(sm + SM_WL);
    float* impS   = (float*)(sm + SM_IMP);
    float* partS  = (float*)(sm + SM_PART);
    float* alphaS = (float*)(sm + SM_ALPHA);
    float* wpart  = (float*)(sm + SM_WPART);

    constexpr int NQ   = N / 8;                          // threads along n
    constexpr int LNQ  = (NQ==64)?6:(NQ==32)?5:(NQ==16)?4:2;
    constexpr int G    = NTHREADS / NQ;                  // q groups
    constexpr int TG   = (G*8 > TPB) ? TPB : G*8;        // tokens per pass
    constexpr int AG   = TG / 8;                         // active q groups
    constexpr int W    = (NQ < 32) ? NQ : 32;            // shuffle width

    const int nq = tid & (NQ - 1);
    const int q  = tid >> LNQ;
    const bool active = (q < AG);

    __syncthreads();
    {
        constexpr int NF4 = N / 4;
        for (int i = tid; i < 64 * NF4; i += NTHREADS) {
            int d = i / NF4, c = i - d * NF4;
            ((float4*)embS)[i] = *(const float4*)(g_embT + (size_t)d * N_TOT + LO + c * 4);
        }
    }
    __syncthreads();

    ull wacc2[8];
    #pragma unroll
    for (int j = 0; j < 8; j++) wacc2[j] = 0ull;

    for (int t0 = 0; t0 < TPB; t0 += TG) {
        ull acc[4][8];
        if (active) {
            #pragma unroll
            for (int u = 0; u < 4; u++)
                #pragma unroll
                for (int j = 0; j < 8; j++) acc[u][j] = 0ull;

            const ull* hrow = HsP + (size_t)(t0 / 2 + q * 4) * HSP_STRIDE;
            const float4* eb4 = (const float4*)embS;
            #pragma unroll 4
            for (int d = 0; d < DSPACE; d++) {
                float4 b0 = eb4[d * (N / 4) + nq * 2];
                float4 b1 = eb4[d * (N / 4) + nq * 2 + 1];
                ull bd[8];
                bd[0]=d_dup(b0.x); bd[1]=d_dup(b0.y); bd[2]=d_dup(b0.z); bd[3]=d_dup(b0.w);
                bd[4]=d_dup(b1.x); bd[5]=d_dup(b1.y); bd[6]=d_dup(b1.z); bd[7]=d_dup(b1.w);
                ull a0 = hrow[d];
                ull a1 = hrow[HSP_STRIDE + d];
                ull a2 = hrow[2*HSP_STRIDE + d];
                ull a3 = hrow[3*HSP_STRIDE + d];
                #pragma unroll
                for (int j = 0; j < 8; j++) {
                    acc[0][j] = d_fma2(a0, bd[j], acc[0][j]);
                    acc[1][j] = d_fma2(a1, bd[j], acc[1][j]);
                    acc[2][j] = d_fma2(a2, bd[j], acc[2][j]);
                    acc[3][j] = d_fma2(a3, bd[j], acc[3][j]);
                }
            }
            // exp in-place (repack into acc) + per-token partial sums
            float ps[8];
            #pragma unroll
            for (int u = 0; u < 4; u++) {
                float sx = 0.0f, sy = 0.0f;
                #pragma unroll
                for (int j = 0; j < 8; j++) {
                    float lo, hi;
                    d_unpack(acc[u][j], lo, hi);
                    float e0 = __expf(lo), e1 = __expf(hi);
                    acc[u][j] = d_pack(e0, e1);
                    sx += e0; sy += e1;
                }
                ps[2*u] = sx; ps[2*u+1] = sy;
            }
            #pragma unroll
            for (int tt = 0; tt < 8; tt++)
                #pragma unroll
                for (int o = W >> 1; o > 0; o >>= 1)
                    ps[tt] += __shfl_xor_sync(0xffffffffu, ps[tt], o);
            if (NQ == 64) {
                if ((tid & 31) == 0) {
                    int half = (tid >> 5) & 1;
                    #pragma unroll
                    for (int tt = 0; tt < 8; tt++) partS[(q*8+tt)*2 + half] = ps[tt];
                }
            } else {
                if (nq == 0) {
                    #pragma unroll
                    for (int tt = 0; tt < 8; tt++) {
                        partS[(q*8+tt)*2]     = ps[tt];
                        partS[(q*8+tt)*2 + 1] = 0.0f;
                    }
                }
            }
        }
        __syncthreads();
        if (tid < TG) alphaS[tid] = impS[t0 + tid] / (partS[2*tid] + partS[2*tid+1]);
        __syncthreads();
        if (active) {
            #pragma unroll
            for (int u = 0; u < 4; u++) {
                ull a2p = d_pack(alphaS[q*8 + 2*u], alphaS[q*8 + 2*u + 1]);
                #pragma unroll
                for (int j = 0; j < 8; j++)
                    wacc2[j] = d_fma2(a2p, acc[u][j], wacc2[j]);
            }
        }
    }
    // deterministic cross-group reduction (no atomics)
    if (active) {
        #pragma unroll
        for (int j = 0; j < 8; j++) {
            float lo, hi;
            d_unpack(wacc2[j], lo, hi);
            wpart[q * N + nq*8 + j] = lo + hi;
        }
    }
    __syncthreads();
    for (int n = tid; n < N; n += NTHREADS) {
        float s = 0.0f;
        #pragma unroll
        for (int g = 0; g < AG; g++) s += wpart[g * N + n];
        w_local[LO + n] = s;
    }
}

// ---------------- finalize helpers ----------------
template<int NN, int KK>
__device__ __forceinline__ void topk_flags(const float* ws, int* flag, int tid) {
    for (int i = tid; i < NN; i += NTHREADS) {
        float wi = ws[i]; int r = 0;
        #pragma unroll 16
        for (int j = 0; j < NN; j++) {
            float wj = ws[j];
            r += (wj > wi) || (wj == wi && j < i);
        }
        flag[i] = (r < KK) ? 1 : 0;
    }
}

// ---------------- main fused kernel ----------------
__global__ void __launch_bounds__(NTHREADS, 1)
main_kernel(const float* __restrict__ x, const float* __restrict__ imp,
            const float* __restrict__ Wm, const float* __restrict__ bias,
            float* __restrict__ out)
{
    extern __shared__ char sm[];
    ull*   XsP    = (ull*)sm;
    float* Ws     = (float*)(sm + 66560);
    ull*   HsP    = (ull*)(sm + SM_HSP);
    float* w_local= (float*)(sm + SM_WL);
    float* impS   = (float*)(sm + SM_IMP);

    const int tid = threadIdx.x;
    const int bb  = blockIdx.x >> 4;
    const int loc = blockIdx.x & 15;
    const int s0  = loc * TPB;

    if (tid < TPB) impS[tid] = imp[bb * SEQ + s0 + tid];

    // ---- GEMM1: H[128][64] = X[128][1024] @ W[1024][64] + b ----
    const int tx = tid & 7;     // n-octet (dspace cols tx*8..tx*8+7)
    const int ty = tid >> 3;    // 0..31, token pairs ty*2, ty*2+1

    ull acc[2][8];
    #pragma unroll
    for (int u = 0; u < 2; u++)
        #pragma unroll
        for (int j = 0; j < 8; j++) acc[u][j] = 0ull;

    const float4* Xg  = (const float4*)(x + (size_t)(bb * SEQ + s0) * DMODEL);
    const float4* Ws4 = (const float4*)Ws;

    for (int p = 0; p < 8; p++) {
        __syncthreads();
        for (int i = tid; i < 64 * 32; i += NTHREADS) {
            int tp = i >> 5, dq = i & 31;
            float4 fa = Xg[(size_t)(2*tp)   * 256 + p*32 + dq];
            float4 fb = Xg[(size_t)(2*tp+1) * 256 + p*32 + dq];
            ull* dst = XsP + (size_t)tp * XSP_STRIDE + dq * 4;
            dst[0] = d_pack(fa.x, fb.x);
            dst[1] = d_pack(fa.y, fb.y);
            dst[2] = d_pack(fa.z, fb.z);
            dst[3] = d_pack(fa.w, fb.w);
        }
        {
            const float4* Wg = (const float4*)(Wm + (size_t)p * 128 * DSPACE);
            float4* d4 = (float4*)Ws;
            for (int i = tid; i < 2048; i += NTHREADS) d4[i] = Wg[i];
        }
        __syncthreads();

        const ull* xrow = XsP + (size_t)(ty * 2) * XSP_STRIDE;
        #pragma unroll 4
        for (int d = 0; d < 128; d++) {
            float4 b0 = Ws4[d * 16 + tx * 2];
            float4 b1 = Ws4[d * 16 + tx * 2 + 1];
            ull bd[8];
            bd[0]=d_dup(b0.x); bd[1]=d_dup(b0.y); bd[2]=d_dup(b0.z); bd[3]=d_dup(b0.w);
            bd[4]=d_dup(b1.x); bd[5]=d_dup(b1.y); bd[6]=d_dup(b1.z); bd[7]=d_dup(b1.w);
            ull a0 = xrow[d];
            ull a1 = xrow[XSP_STRIDE + d];
            #pragma unroll
            for (int j = 0; j < 8; j++) {
                acc[0][j] = d_fma2(a0, bd[j], acc[0][j]);
                acc[1][j] = d_fma2(a1, bd[j], acc[1][j]);
            }
        }
    }
    {
        #pragma unroll
        for (int j = 0; j < 8; j++) {
            ull bj = d_dup(bias[tx * 8 + j]);
            #pragma unroll
            for (int u = 0; u < 2; u++) acc[u][j] = d_add2(acc[u][j], bj);
        }
        #pragma unroll
        for (int u = 0; u < 2; u++)
            #pragma unroll
            for (int j = 0; j < 8; j++)
                HsP[(size_t)(ty*2 + u) * HSP_STRIDE + tx*8 + j] = acc[u][j];
    }

    // ---- GEMM2 + softmax + routing per slice ----
    do_slice<N_QK, 0>(sm, tid);
    do_slice<N_V,  N_QK>(sm, tid);
    do_slice<N_REL, N_QK + N_V>(sm, tid);
    do_slice<N_VAL, N_QK + N_V + N_REL>(sm, tid);

    __syncthreads();
    for (int i = tid; i < N_TOT; i += NTHREADS)
        g_wpart[blockIdx.x][i] = w_local[i];

    // ---- completion counter: last block of this batch finalizes ----
    __shared__ int lastFlag;
    __threadfence();
    if (tid == 0) {
        int old = atomicAdd(&g_cnt[bb], 1);
        lastFlag = (old == 15);
    }
    __syncthreads();
    if (!lastFlag) return;

    // finalize: deterministic sum of the 16 partials, then top-k tasks
    float* sws  = (float*)sm;                 // [928]
    int*   flag = (int*)(sm + 4096);          // [512]
    for (int n = tid; n < N_TOT; n += NTHREADS) {
        float s = 0.0f;
        #pragma unroll
        for (int l = 0; l < 16; l++) s += g_wpart[bb * 16 + l][n];
        sws[n] = s;
    }
    __syncthreads();

    // raw w copies
    for (int i = tid; i < N_QK; i += NTHREADS) out[OFF_WQK + bb * N_QK + i] = sws[i];
    for (int i = tid; i < N_V;  i += NTHREADS) out[OFF_WV  + bb * N_V  + i] = sws[N_QK + i];

    // task 1: qk top-64 indices
    topk_flags<N_QK, K_QK>(sws, flag, tid);
    __syncthreads();
    for (int i = tid; i < N_QK; i += NTHREADS) {
        if (flag[i]) {
            int pos = 0;
            for (int j = 0; j < i; j++) pos += flag[j];
            out[OFF_IDXQK + bb * K_QK + pos] = (float)i;
        }
    }
    __syncthreads();
    // task 2: v top-32 indices
    topk_flags<N_V, K_V>(sws + N_QK, flag, tid);
    __syncthreads();
    for (int i = tid; i < N_V; i += NTHREADS) {
        if (flag[i]) {
            int pos = 0;
            for (int j = 0; j < i; j++) pos += flag[j];
            out[OFF_IDXV + bb * K_V + pos] = (float)i;
        }
    }
    __syncthreads();
    // task 3: rel sparsify top-16 (rw_Q == rw_K)
    topk_flags<N_REL, K_REL>(sws + N_QK + N_V, flag, tid);
    __syncthreads();
    for (int i = tid; i < N_REL; i += NTHREADS) {
        float v = flag[i] ? sws[N_QK + N_V + i] : 0.0f;
        out[OFF_RWQ + bb * N_REL + i] = v;
        out[OFF_RWK + bb * N_REL + i] = v;
    }
    __syncthreads();
    // task 4: val sparsify top-3
    topk_flags<N_VAL, K_VAL>(sws + N_QK + N_V + N_REL, flag, tid);
    __syncthreads();
    for (int i = tid; i < N_VAL; i += NTHREADS)
        out[OFF_VW + bb * N_VAL + i] = flag[i] ? sws[N_QK + N_V + N_REL + i] : 0.0f;
}

extern "C" void kernel_launch(void* const* d_in, const int* in_sizes, int n_in,
                              void* d_out, int out_size) {
    const float* x    = (const float*)d_in[0];
    const float* imp  = (const float*)d_in[1];
    const float* Wm   = (const float*)d_in[2];
    const float* bias = (const float*)d_in[3];
    const float* emb  = (const float*)d_in[4];
    float* out = (float*)d_out;

    cudaFuncSetAttribute(main_kernel, cudaFuncAttributeMaxDynamicSharedMemorySize, SMEM_BYTES);

    prep_kernel<<<N_TOT, 64>>>(emb);
    main_kernel<<<NBLOCKS, NTHREADS, SMEM_BYTES>>>(x, imp, Wm, bias, out);
}

// round 5
// speedup vs baseline: 1.2579x; 1.2579x over previous
#include <cuda_runtime.h>
#include <math.h>

typedef unsigned long long ull;

// Problem constants
#define BATCH   8
#define SEQ     2048
#define DMODEL  1024
#define DSPACE  64
#define N_QK    512
#define N_V     256
#define N_REL   128
#define N_VAL   32
#define N_TOT   928
#define K_QK    64
#define K_V     32
#define K_REL   16
#define K_VAL   3

#define TPB      128
#define NTHREADS 256
#define NBLOCKS  (BATCH * SEQ / TPB)      // 128, 16 per batch

// Output layout (float32, reference return order)
#define OFF_IDXQK 0
#define OFF_IDXV  (OFF_IDXQK + BATCH*K_QK)
#define OFF_RWQ   (OFF_IDXV  + BATCH*K_V)
#define OFF_RWK   (OFF_RWQ   + BATCH*N_REL)
#define OFF_VW    (OFF_RWK   + BATCH*N_REL)
#define OFF_WQK   (OFF_VW    + BATCH*N_VAL)
#define OFF_WV    (OFF_WQK   + BATCH*N_QK)

// Shared memory byte offsets
#define SM_HSP   131072     // HsP: ull[64][66] = 33792
#define SM_WL    164864     // w_local float[928]
#define SM_IMP   168576     // impS float[128]
#define SM_PART  169088     // partS float[256]
#define SM_ALPHA 170112     // alphaS float[128]
#define SM_WPART 170624     // wpart float[2048] = 8192
#define SMEM_BYTES 178816

#define XSP_STRIDE 130
#define HSP_STRIDE 66

// device scratch (no allocation allowed)
__device__ float g_embT[DSPACE * N_TOT];        // normalized emb transposed [d][n]
__device__ float g_wpart[NBLOCKS][N_TOT];       // per-block partial w
__device__ int   g_cnt[BATCH];                  // completion counters

// ---------------- f32x2 helpers ----------------
__device__ __forceinline__ ull d_pack(float x, float y) {
    ull r; asm("mov.b64 %0, {%1, %2};" : "=l"(r) : "f"(x), "f"(y)); return r;
}
__device__ __forceinline__ ull d_dup(float x) {
    ull r; asm("mov.b64 %0, {%1, %1};" : "=l"(r) : "f"(x)); return r;
}
__device__ __forceinline__ void d_unpack(ull v, float& x, float& y) {
    asm("mov.b64 {%0, %1}, %2;" : "=f"(x), "=f"(y) : "l"(v));
}
__device__ __forceinline__ ull d_fma2(ull a, ull b, ull c) {
    ull d; asm("fma.rn.f32x2 %0, %1, %2, %3;" : "=l"(d) : "l"(a), "l"(b), "l"(c)); return d;
}
__device__ __forceinline__ ull d_add2(ull a, ull b) {
    ull d; asm("add.rn.f32x2 %0, %1, %2;" : "=l"(d) : "l"(a), "l"(b)); return d;
}

// ---------------- prep: normalize emb (transposed) + reset counters ----------------
__global__ void prep_kernel(const float* __restrict__ emb) {
    int r = blockIdx.x;     // neuron 0..927
    int t = threadIdx.x;    // dim 0..63
    if (r == 0 && t < BATCH) g_cnt[t] = 0;
    __shared__ float s[64];
    float v = emb[r * DSPACE + t];
    s[t] = v * v;
    __syncthreads();
    #pragma unroll
    for (int o = 32; o > 0; o >>= 1) {
        if (t < o) s[t] += s[t + o];
        __syncthreads();
    }
    float norm = sqrtf(s[0]);
    g_embT[t * N_TOT + r] = v / norm;
}

// ---------------- GEMM2 + softmax + routed-weight slice ----------------
template<int N, int LO>
__device__ __forceinline__ void do_slice(char* sm, int tid) {
    float* embS   = (float*)sm;
    ull*   HsP    = (ull*)(sm + SM_HSP);
    float* w_local= (float*)(sm + SM_WL);
    float* impS   = (float*)(sm + SM_IMP);
    float* partS  = (float*)(sm + SM_PART);
    float* alphaS = (float*)(sm + SM_ALPHA);
    float* wpart  = (float*)(sm + SM_WPART);

    constexpr int NQ   = N / 8;                          // threads along n
    constexpr int LNQ  = (NQ==64)?6:(NQ==32)?5:(NQ==16)?4:2;
    constexpr int G    = NTHREADS / NQ;                  // q groups
    constexpr int TG   = (G*8 > TPB) ? TPB : G*8;        // tokens per pass
    constexpr int AG   = TG / 8;                         // active q groups
    constexpr int W    = (NQ < 32) ? NQ : 32;            // shuffle width
    constexpr int N4   = N / 4;

    const int nq = tid & (NQ - 1);
    const int q  = tid >> LNQ;
    const bool active = (q < AG);

    __syncthreads();
    {
        for (int i = tid; i < 64 * N4; i += NTHREADS) {
            int d = i / N4, c = i - d * N4;
            ((float4*)embS)[i] = *(const float4*)(g_embT + (size_t)d * N_TOT + LO + c * 4);
        }
    }
    __syncthreads();

    ull wacc2[8];
    #pragma unroll
    for (int j = 0; j < 8; j++) wacc2[j] = 0ull;

    for (int t0 = 0; t0 < TPB; t0 += TG) {
        ull acc[4][8];
        if (active) {
            #pragma unroll
            for (int u = 0; u < 4; u++)
                #pragma unroll
                for (int j = 0; j < 8; j++) acc[u][j] = 0ull;

            const ull* hrow = HsP + (size_t)(t0 / 2 + q * 4) * HSP_STRIDE;
            const float4* eb4 = (const float4*)embS;
            #pragma unroll 4
            for (int d = 0; d < DSPACE; d++) {
                // conflict-free: 16B lane stride; this thread's neurons are
                // {nq*4..nq*4+3} and {N/2 + nq*4 .. +3}
                float4 b0 = eb4[d * N4 + nq];
                float4 b1 = eb4[d * N4 + NQ + nq];
                ull bd[8];
                bd[0]=d_dup(b0.x); bd[1]=d_dup(b0.y); bd[2]=d_dup(b0.z); bd[3]=d_dup(b0.w);
                bd[4]=d_dup(b1.x); bd[5]=d_dup(b1.y); bd[6]=d_dup(b1.z); bd[7]=d_dup(b1.w);
                ull a0 = hrow[d];
                ull a1 = hrow[HSP_STRIDE + d];
                ull a2 = hrow[2*HSP_STRIDE + d];
                ull a3 = hrow[3*HSP_STRIDE + d];
                #pragma unroll
                for (int j = 0; j < 8; j++) {
                    acc[0][j] = d_fma2(a0, bd[j], acc[0][j]);
                    acc[1][j] = d_fma2(a1, bd[j], acc[1][j]);
                    acc[2][j] = d_fma2(a2, bd[j], acc[2][j]);
                    acc[3][j] = d_fma2(a3, bd[j], acc[3][j]);
                }
            }
            // exp in-place (repack into acc) + per-token partial sums
            float ps[8];
            #pragma unroll
            for (int u = 0; u < 4; u++) {
                float sx = 0.0f, sy = 0.0f;
                #pragma unroll
                for (int j = 0; j < 8; j++) {
                    float lo, hi;
                    d_unpack(acc[u][j], lo, hi);
                    float e0 = __expf(lo), e1 = __expf(hi);
                    acc[u][j] = d_pack(e0, e1);
                    sx += e0; sy += e1;
                }
                ps[2*u] = sx; ps[2*u+1] = sy;
            }
            #pragma unroll
            for (int tt = 0; tt < 8; tt++)
                #pragma unroll
                for (int o = W >> 1; o > 0; o >>= 1)
                    ps[tt] += __shfl_xor_sync(0xffffffffu, ps[tt], o);
            if (NQ == 64) {
                if ((tid & 31) == 0) {
                    int half = (tid >> 5) & 1;
                    #pragma unroll
                    for (int tt = 0; tt < 8; tt++) partS[(q*8+tt)*2 + half] = ps[tt];
                }
            } else {
                if (nq == 0) {
                    #pragma unroll
                    for (int tt = 0; tt < 8; tt++) {
                        partS[(q*8+tt)*2]     = ps[tt];
                        partS[(q*8+tt)*2 + 1] = 0.0f;
                    }
                }
            }
        }
        __syncthreads();
        if (tid < TG) alphaS[tid] = impS[t0 + tid] / (partS[2*tid] + partS[2*tid+1]);
        __syncthreads();
        if (active) {
            #pragma unroll
            for (int u = 0; u < 4; u++) {
                ull a2p = d_pack(alphaS[q*8 + 2*u], alphaS[q*8 + 2*u + 1]);
                #pragma unroll
                for (int j = 0; j < 8; j++)
                    wacc2[j] = d_fma2(a2p, acc[u][j], wacc2[j]);
            }
        }
    }
    // deterministic cross-group reduction (no atomics)
    if (active) {
        #pragma unroll
        for (int j = 0; j < 8; j++) {
            float lo, hi;
            d_unpack(wacc2[j], lo, hi);
            int n = (j < 4) ? (nq*4 + j) : (N/2 + nq*4 + (j-4));
            wpart[q * N + n] = lo + hi;
        }
    }
    __syncthreads();
    for (int n = tid; n < N; n += NTHREADS) {
        float s = 0.0f;
        #pragma unroll
        for (int g = 0; g < AG; g++) s += wpart[g * N + n];
        w_local[LO + n] = s;
    }
}

// ---------------- finalize helpers ----------------
template<int NN, int KK>
__device__ __forceinline__ void topk_flags(const float* ws, int* flag, int tid) {
    for (int i = tid; i < NN; i += NTHREADS) {
        float wi = ws[i]; int r = 0;
        #pragma unroll 16
        for (int j = 0; j < NN; j++) {
            float wj = ws[j];
            r += (wj > wi) || (wj == wi && j < i);
        }
        flag[i] = (r < KK) ? 1 : 0;
    }
}

// ---------------- main fused kernel ----------------
__global__ void __launch_bounds__(NTHREADS, 1)
main_kernel(const float* __restrict__ x, const float* __restrict__ imp,
            const float* __restrict__ Wm, const float* __restrict__ bias,
            float* __restrict__ out)
{
    extern __shared__ char sm[];
    ull*   XsP    = (ull*)sm;
    float* Ws     = (float*)(sm + 66560);
    ull*   HsP    = (ull*)(sm + SM_HSP);
    float* w_local= (float*)(sm + SM_WL);
    float* impS   = (float*)(sm + SM_IMP);

    const int tid = threadIdx.x;
    const int bb  = blockIdx.x >> 4;
    const int loc = blockIdx.x & 15;
    const int s0  = loc * TPB;

    if (tid < TPB) impS[tid] = imp[bb * SEQ + s0 + tid];

    // ---- GEMM1: H[128][64] = X[128][1024] @ W[1024][64] + b ----
    const int tx = tid & 7;     // dspace cols {tx*4..+3} and {32+tx*4..+3}
    const int ty = tid >> 3;    // 0..31, token pairs ty*2, ty*2+1

    ull acc[2][8];
    #pragma unroll
    for (int u = 0; u < 2; u++)
        #pragma unroll
        for (int j = 0; j < 8; j++) acc[u][j] = 0ull;

    const float4* Xg  = (const float4*)(x + (size_t)(bb * SEQ + s0) * DMODEL);
    const float4* Ws4 = (const float4*)Ws;

    for (int p = 0; p < 8; p++) {
        __syncthreads();
        // XsP permuted layout: slot = dq + 32*c holds logical d = dq*4 + c
        // -> STS lane stride 8B, conflict-free
        for (int i = tid; i < 64 * 32; i += NTHREADS) {
            int tp = i >> 5, dq = i & 31;
            float4 fa = Xg[(size_t)(2*tp)   * 256 + p*32 + dq];
            float4 fb = Xg[(size_t)(2*tp+1) * 256 + p*32 + dq];
            ull* dst = XsP + (size_t)tp * XSP_STRIDE + dq;
            dst[0]  = d_pack(fa.x, fb.x);
            dst[32] = d_pack(fa.y, fb.y);
            dst[64] = d_pack(fa.z, fb.z);
            dst[96] = d_pack(fa.w, fb.w);
        }
        {
            const float4* Wg = (const float4*)(Wm + (size_t)p * 128 * DSPACE);
            float4* d4 = (float4*)Ws;
            for (int i = tid; i < 2048; i += NTHREADS) d4[i] = Wg[i];
        }
        __syncthreads();

        const ull* xrow = XsP + (size_t)(ty * 2) * XSP_STRIDE;
        #pragma unroll
        for (int c = 0; c < 4; c++) {
            #pragma unroll 8
            for (int i = 0; i < 32; i++) {
                const int slot = c * 32 + i;
                const int d    = i * 4 + c;
                // conflict-free: 16B lane stride over 8 tx
                float4 b0 = Ws4[d * 16 + tx];
                float4 b1 = Ws4[d * 16 + 8 + tx];
                ull bd[8];
                bd[0]=d_dup(b0.x); bd[1]=d_dup(b0.y); bd[2]=d_dup(b0.z); bd[3]=d_dup(b0.w);
                bd[4]=d_dup(b1.x); bd[5]=d_dup(b1.y); bd[6]=d_dup(b1.z); bd[7]=d_dup(b1.w);
                ull a0 = xrow[slot];
                ull a1 = xrow[XSP_STRIDE + slot];
                #pragma unroll
                for (int j = 0; j < 8; j++) {
                    acc[0][j] = d_fma2(a0, bd[j], acc[0][j]);
                    acc[1][j] = d_fma2(a1, bd[j], acc[1][j]);
                }
            }
        }
    }
    {
        // column mapping: j<4 -> n = tx*4+j ; j>=4 -> n = 32 + tx*4 + (j-4)
        #pragma unroll
        for (int j = 0; j < 8; j++) {
            int n = (j < 4) ? (tx*4 + j) : (32 + tx*4 + (j-4));
            ull bj = d_dup(bias[n]);
            #pragma unroll
            for (int u = 0; u < 2; u++) {
                ull v = d_add2(acc[u][j], bj);
                HsP[(size_t)(ty*2 + u) * HSP_STRIDE + n] = v;
            }
        }
    }

    // ---- GEMM2 + softmax + routing per slice ----
    do_slice<N_QK, 0>(sm, tid);
    do_slice<N_V,  N_QK>(sm, tid);
    do_slice<N_REL, N_QK + N_V>(sm, tid);
    do_slice<N_VAL, N_QK + N_V + N_REL>(sm, tid);

    __syncthreads();
    for (int i = tid; i < N_TOT; i += NTHREADS)
        g_wpart[blockIdx.x][i] = w_local[i];

    // ---- completion counter: last block of this batch finalizes ----
    __shared__ int lastFlag;
    __threadfence();
    if (tid == 0) {
        int old = atomicAdd(&g_cnt[bb], 1);
        lastFlag = (old == 15);
    }
    __syncthreads();
    if (!lastFlag) return;

    // finalize: deterministic sum of the 16 partials, then top-k tasks
    float* sws  = (float*)sm;                 // [928]
    int*   flag = (int*)(sm + 4096);          // [512]
    for (int n = tid; n < N_TOT; n += NTHREADS) {
        float s = 0.0f;
        #pragma unroll
        for (int l = 0; l < 16; l++) s += g_wpart[bb * 16 + l][n];
        sws[n] = s;
    }
    __syncthreads();

    // raw w copies
    for (int i = tid; i < N_QK; i += NTHREADS) out[OFF_WQK + bb * N_QK + i] = sws[i];
    for (int i = tid; i < N_V;  i += NTHREADS) out[OFF_WV  + bb * N_V  + i] = sws[N_QK + i];

    // task 1: qk top-64 indices
    topk_flags<N_QK, K_QK>(sws, flag, tid);
    __syncthreads();
    for (int i = tid; i < N_QK; i += NTHREADS) {
        if (flag[i]) {
            int pos = 0;
            for (int j = 0; j < i; j++) pos += flag[j];
            out[OFF_IDXQK + bb * K_QK + pos] = (float)i;
        }
    }
    __syncthreads();
    // task 2: v top-32 indices
    topk_flags<N_V, K_V>(sws + N_QK, flag, tid);
    __syncthreads();
    for (int i = tid; i < N_V; i += NTHREADS) {
        if (flag[i]) {
            int pos = 0;
            for (int j = 0; j < i; j++) pos += flag[j];
            out[OFF_IDXV + bb * K_V + pos] = (float)i;
        }
    }
    __syncthreads();
    // task 3: rel sparsify top-16 (rw_Q == rw_K)
    topk_flags<N_REL, K_REL>(sws + N_QK + N_V, flag, tid);
    __syncthreads();
    for (int i = tid; i < N_REL; i += NTHREADS) {
        float v = flag[i] ? sws[N_QK + N_V + i] : 0.0f;
        out[OFF_RWQ + bb * N_REL + i] = v;
        out[OFF_RWK + bb * N_REL + i] = v;
    }
    __syncthreads();
    // task 4: val sparsify top-3
    topk_flags<N_VAL, K_VAL>(sws + N_QK + N_V + N_REL, flag, tid);
    __syncthreads();
    for (int i = tid; i < N_VAL; i += NTHREADS)
        out[OFF_VW + bb * N_VAL + i] = flag[i] ? sws[N_QK + N_V + N_REL + i] : 0.0f;
}

extern "C" void kernel_launch(void* const* d_in, const int* in_sizes, int n_in,
                              void* d_out, int out_size) {
    const float* x    = (const float*)d_in[0];
    const float* imp  = (const float*)d_in[1];
    const float* Wm   = (const float*)d_in[2];
    const float* bias = (const float*)d_in[3];
    const float* emb  = (const float*)d_in[4];
    float* out = (float*)d_out;

    cudaFuncSetAttribute(main_kernel, cudaFuncAttributeMaxDynamicSharedMemorySize, SMEM_BYTES);

    prep_kernel<<<N_TOT, 64>>>(emb);
    main_kernel<<<NBLOCKS, NTHREADS, SMEM_BYTES>>>(x, imp, Wm, bias, out);
}

// round 6
// speedup vs baseline: 1.2787x; 1.0166x over previous
#include <cuda_runtime.h>
#include <math.h>

typedef unsigned long long ull;

// Problem constants
#define BATCH   8
#define SEQ     2048
#define DMODEL  1024
#define DSPACE  64
#define N_QK    512
#define N_V     256
#define N_REL   128
#define N_VAL   32
#define N_TOT   928
#define K_QK    64
#define K_V     32
#define K_REL   16
#define K_VAL   3

#define TPB      128
#define NTHREADS 512
#define NBLOCKS  (BATCH * SEQ / TPB)      // 128, 16 per batch

// Output layout (float32, reference return order)
#define OFF_IDXQK 0
#define OFF_IDXV  (OFF_IDXQK + BATCH*K_QK)
#define OFF_RWQ   (OFF_IDXV  + BATCH*K_V)
#define OFF_RWK   (OFF_RWQ   + BATCH*N_REL)
#define OFF_VW    (OFF_RWK   + BATCH*N_REL)
#define OFF_WQK   (OFF_VW    + BATCH*N_VAL)
#define OFF_WV    (OFF_WQK   + BATCH*N_QK)

// Shared memory byte offsets
// U region [0,131072): XsP ull[64][130] (66560) | Ws float[128][64] at 66560 (32768)
//                      aliased by: GEMM1 exchange buf ull[64tp][4ks][64c] (131072)
//                      aliased by: embS float[64][<=512] (<=131072)
//                      aliased by: finalize sws/flag
#define SM_HSP   131072     // HsP: ull[64][66] = 33792
#define SM_WL    164864     // w_local float[928]
#define SM_IMP   168576     // impS float[128]
#define SM_PART  169088     // partS float[256]
#define SM_ALPHA 170112     // alphaS float[128]
#define SM_WPART 170624     // wpart float[16][max 512] = 16384 (QK uses 8x512)
#define SM_FLAGW 187008
#define SMEM_BYTES 187136

#define XSP_STRIDE 130
#define HSP_STRIDE 66

// device scratch (no allocation allowed)
__device__ float g_embT[DSPACE * N_TOT];        // normalized emb transposed [d][n]
__device__ float g_wpart[NBLOCKS][N_TOT];       // per-block partial w
__device__ int   g_cnt[BATCH];                  // completion counters

// ---------------- f32x2 helpers ----------------
__device__ __forceinline__ ull d_pack(float x, float y) {
    ull r; asm("mov.b64 %0, {%1, %2};" : "=l"(r) : "f"(x), "f"(y)); return r;
}
__device__ __forceinline__ ull d_dup(float x) {
    ull r; asm("mov.b64 %0, {%1, %1};" : "=l"(r) : "f"(x)); return r;
}
__device__ __forceinline__ void d_unpack(ull v, float& x, float& y) {
    asm("mov.b64 {%0, %1}, %2;" : "=f"(x), "=f"(y) : "l"(v));
}
__device__ __forceinline__ ull d_fma2(ull a, ull b, ull c) {
    ull d; asm("fma.rn.f32x2 %0, %1, %2, %3;" : "=l"(d) : "l"(a), "l"(b), "l"(c)); return d;
}
__device__ __forceinline__ ull d_add2(ull a, ull b) {
    ull d; asm("add.rn.f32x2 %0, %1, %2;" : "=l"(d) : "l"(a), "l"(b)); return d;
}

// ---------------- prep: normalize emb (transposed) + reset counters ----------------
__global__ void prep_kernel(const float* __restrict__ emb) {
    int r = blockIdx.x;     // neuron 0..927
    int t = threadIdx.x;    // dim 0..63
    if (r == 0 && t < BATCH) g_cnt[t] = 0;
    __shared__ float s[64];
    float v = emb[r * DSPACE + t];
    s[t] = v * v;
    __syncthreads();
    #pragma unroll
    for (int o = 32; o > 0; o >>= 1) {
        if (t < o) s[t] += s[t + o];
        __syncthreads();
    }
    float norm = sqrtf(s[0]);
    g_embT[t * N_TOT + r] = v / norm;
}

// ---------------- GEMM2 + softmax + routed-weight slice ----------------
template<int N, int LO>
__device__ __forceinline__ void do_slice(char* sm, int tid) {
    float* embS   = (float*)sm;
    ull*   HsP    = (ull*)(sm + SM_HSP);
    float* w_local= (float*)(sm + SM_WL);
    float* impS   = (float*)(sm + SM_IMP);
    float* partS  = (float*)(sm + SM_PART);
    float* alphaS = (float*)(sm + SM_ALPHA);
    float* wpart  = (float*)(sm + SM_WPART);

    constexpr int NQ   = N / 8;                          // threads along n
    constexpr int LNQ  = (NQ==64)?6:(NQ==32)?5:(NQ==16)?4:2;
    constexpr int G    = NTHREADS / NQ;                  // q groups
    constexpr int TG   = (G*8 > TPB) ? TPB : G*8;        // tokens per pass
    constexpr int AG   = TG / 8;                         // active q groups
    constexpr int W    = (NQ < 32) ? NQ : 32;            // shuffle width
    constexpr int N4   = N / 4;

    const int nq = tid & (NQ - 1);
    const int q  = tid >> LNQ;
    const bool active = (q < AG);

    __syncthreads();
    {
        for (int i = tid; i < 64 * N4; i += NTHREADS) {
            int d = i / N4, c = i - d * N4;
            ((float4*)embS)[i] = *(const float4*)(g_embT + (size_t)d * N_TOT + LO + c * 4);
        }
    }
    __syncthreads();

    ull wacc2[8];
    #pragma unroll
    for (int j = 0; j < 8; j++) wacc2[j] = 0ull;

    for (int t0 = 0; t0 < TPB; t0 += TG) {
        ull acc[4][8];
        if (active) {
            #pragma unroll
            for (int u = 0; u < 4; u++)
                #pragma unroll
                for (int j = 0; j < 8; j++) acc[u][j] = 0ull;

            const ull* hrow = HsP + (size_t)(t0 / 2 + q * 4) * HSP_STRIDE;
            const float4* eb4 = (const float4*)embS;
            #pragma unroll 4
            for (int d = 0; d < DSPACE; d++) {
                // conflict-free: 16B lane stride; this thread's neurons are
                // {nq*4..nq*4+3} and {N/2 + nq*4 .. +3}
                float4 b0 = eb4[d * N4 + nq];
                float4 b1 = eb4[d * N4 + NQ + nq];
                ull bd[8];
                bd[0]=d_dup(b0.x); bd[1]=d_dup(b0.y); bd[2]=d_dup(b0.z); bd[3]=d_dup(b0.w);
                bd[4]=d_dup(b1.x); bd[5]=d_dup(b1.y); bd[6]=d_dup(b1.z); bd[7]=d_dup(b1.w);
                ull a0 = hrow[d];
                ull a1 = hrow[HSP_STRIDE + d];
                ull a2 = hrow[2*HSP_STRIDE + d];
                ull a3 = hrow[3*HSP_STRIDE + d];
                #pragma unroll
                for (int j = 0; j < 8; j++) {
                    acc[0][j] = d_fma2(a0, bd[j], acc[0][j]);
                    acc[1][j] = d_fma2(a1, bd[j], acc[1][j]);
                    acc[2][j] = d_fma2(a2, bd[j], acc[2][j]);
                    acc[3][j] = d_fma2(a3, bd[j], acc[3][j]);
                }
            }
            // exp in-place (repack into acc) + per-token partial sums
            float ps[8];
            #pragma unroll
            for (int u = 0; u < 4; u++) {
                float sx = 0.0f, sy = 0.0f;
                #pragma unroll
                for (int j = 0; j < 8; j++) {
                    float lo, hi;
                    d_unpack(acc[u][j], lo, hi);
                    float e0 = __expf(lo), e1 = __expf(hi);
                    acc[u][j] = d_pack(e0, e1);
                    sx += e0; sy += e1;
                }
                ps[2*u] = sx; ps[2*u+1] = sy;
            }
            #pragma unroll
            for (int tt = 0; tt < 8; tt++)
                #pragma unroll
                for (int o = W >> 1; o > 0; o >>= 1)
                    ps[tt] += __shfl_xor_sync(0xffffffffu, ps[tt], o);
            if (NQ == 64) {
                if ((tid & 31) == 0) {
                    int half = (tid >> 5) & 1;
                    #pragma unroll
                    for (int tt = 0; tt < 8; tt++) partS[(q*8+tt)*2 + half] = ps[tt];
                }
            } else {
                if (nq == 0) {
                    #pragma unroll
                    for (int tt = 0; tt < 8; tt++) {
                        partS[(q*8+tt)*2]     = ps[tt];
                        partS[(q*8+tt)*2 + 1] = 0.0f;
                    }
                }
            }
        }
        __syncthreads();
        if (tid < TG) alphaS[tid] = impS[t0 + tid] / (partS[2*tid] + partS[2*tid+1]);
        __syncthreads();
        if (active) {
            #pragma unroll
            for (int u = 0; u < 4; u++) {
                ull a2p = d_pack(alphaS[q*8 + 2*u], alphaS[q*8 + 2*u + 1]);
                #pragma unroll
                for (int j = 0; j < 8; j++)
                    wacc2[j] = d_fma2(a2p, acc[u][j], wacc2[j]);
            }
        }
    }
    // deterministic cross-group reduction (no atomics)
    if (active) {
        #pragma unroll
        for (int j = 0; j < 8; j++) {
            float lo, hi;
            d_unpack(wacc2[j], lo, hi);
            int n = (j < 4) ? (nq*4 + j) : (N/2 + nq*4 + (j-4));
            wpart[q * N + n] = lo + hi;
        }
    }
    __syncthreads();
    for (int n = tid; n < N; n += NTHREADS) {
        float s = 0.0f;
        #pragma unroll
        for (int g = 0; g < AG; g++) s += wpart[g * N + n];
        w_local[LO + n] = s;
    }
}

// ---------------- finalize helpers ----------------
template<int NN, int KK>
__device__ __forceinline__ void topk_flags(const float* ws, int* flag, int tid) {
    for (int i = tid; i < NN; i += NTHREADS) {
        float wi = ws[i]; int r = 0;
        #pragma unroll 16
        for (int j = 0; j < NN; j++) {
            float wj = ws[j];
            r += (wj > wi) || (wj == wi && j < i);
        }
        flag[i] = (r < KK) ? 1 : 0;
    }
}

// ---------------- main fused kernel ----------------
__global__ void __launch_bounds__(NTHREADS, 1)
main_kernel(const float* __restrict__ x, const float* __restrict__ imp,
            const float* __restrict__ Wm, const float* __restrict__ bias,
            float* __restrict__ out)
{
    extern __shared__ char sm[];
    ull*   XsP    = (ull*)sm;
    float* Ws     = (float*)(sm + 66560);
    ull*   xbuf   = (ull*)sm;                   // GEMM1 exchange buffer (aliases XsP/Ws)
    ull*   HsP    = (ull*)(sm + SM_HSP);
    float* w_local= (float*)(sm + SM_WL);
    float* impS   = (float*)(sm + SM_IMP);

    const int tid = threadIdx.x;
    const int bb  = blockIdx.x >> 4;
    const int loc = blockIdx.x & 15;
    const int s0  = loc * TPB;

    if (tid < TPB) impS[tid] = imp[bb * SEQ + s0 + tid];

    // ---- GEMM1: H[128][64] = X[128][1024] @ W[1024][64] + b ----
    // 512 threads = ks(2b) | tg(4b) | cg(3b); k-split 4, tiles 8tok x 8col
    const int cg = tid & 7;         // dspace cols {cg*4..+3} and {32+cg*4..+3}
    const int tg = (tid >> 3) & 15; // token pairs tg*4 .. tg*4+3
    const int ks = tid >> 7;        // d-quarter within each chunk

    ull acc[4][8];
    #pragma unroll
    for (int u = 0; u < 4; u++)
        #pragma unroll
        for (int j = 0; j < 8; j++) acc[u][j] = 0ull;

    const float4* Xg  = (const float4*)(x + (size_t)(bb * SEQ + s0) * DMODEL);
    const float4* Ws4 = (const float4*)Ws;

    for (int p = 0; p < 8; p++) {
        __syncthreads();
        // XsP permuted layout: slot = dq + 32*c holds logical d = dq*4 + c
        // -> STS lane stride 8B, conflict-free
        for (int i = tid; i < 64 * 32; i += NTHREADS) {
            int tp = i >> 5, dq = i & 31;
            float4 fa = Xg[(size_t)(2*tp)   * 256 + p*32 + dq];
            float4 fb = Xg[(size_t)(2*tp+1) * 256 + p*32 + dq];
            ull* dst = XsP + (size_t)tp * XSP_STRIDE + dq;
            dst[0]  = d_pack(fa.x, fb.x);
            dst[32] = d_pack(fa.y, fb.y);
            dst[64] = d_pack(fa.z, fb.z);
            dst[96] = d_pack(fa.w, fb.w);
        }
        {
            const float4* Wg = (const float4*)(Wm + (size_t)p * 128 * DSPACE);
            float4* d4 = (float4*)Ws;
            for (int i = tid; i < 2048; i += NTHREADS) d4[i] = Wg[i];
        }
        __syncthreads();

        const ull* xrow = XsP + (size_t)(tg * 4) * XSP_STRIDE;
        #pragma unroll 8
        for (int i = 0; i < 32; i++) {
            const int slot = ks * 32 + i;           // this ks's d-subset
            const int d    = i * 4 + ks;
            // conflict-free: 16B lane stride over 8 cg
            float4 b0 = Ws4[d * 16 + cg];
            float4 b1 = Ws4[d * 16 + 8 + cg];
            ull bd[8];
            bd[0]=d_dup(b0.x); bd[1]=d_dup(b0.y); bd[2]=d_dup(b0.z); bd[3]=d_dup(b0.w);
            bd[4]=d_dup(b1.x); bd[5]=d_dup(b1.y); bd[6]=d_dup(b1.z); bd[7]=d_dup(b1.w);
            ull a0 = xrow[slot];
            ull a1 = xrow[XSP_STRIDE + slot];
            ull a2 = xrow[2*XSP_STRIDE + slot];
            ull a3 = xrow[3*XSP_STRIDE + slot];
            #pragma unroll
            for (int j = 0; j < 8; j++) {
                acc[0][j] = d_fma2(a0, bd[j], acc[0][j]);
                acc[1][j] = d_fma2(a1, bd[j], acc[1][j]);
                acc[2][j] = d_fma2(a2, bd[j], acc[2][j]);
                acc[3][j] = d_fma2(a3, bd[j], acc[3][j]);
            }
        }
    }
    // ---- k-split exchange: buf[tp][ks][col] (131072 B, aliases XsP/Ws) ----
    __syncthreads();
    {
        #pragma unroll
        for (int u = 0; u < 4; u++) {
            const int tp = tg * 4 + u;
            #pragma unroll
            for (int j = 0; j < 8; j++) {
                int col = (j < 4) ? (cg*4 + j) : (32 + cg*4 + (j-4));
                xbuf[(size_t)tp * 256 + ks * 64 + col] = acc[u][j];
            }
        }
    }
    __syncthreads();
    // reduce 4 partials + bias -> HsP[tp][col]
    {
        #pragma unroll
        for (int k = 0; k < 8; k++) {
            int L = tid * 8 + k;            // 0..4095
            int tp = L >> 6, col = L & 63;
            ull s = d_add2(d_add2(xbuf[(size_t)tp*256 + col],
                                  xbuf[(size_t)tp*256 + 64 + col]),
                           d_add2(xbuf[(size_t)tp*256 + 128 + col],
                                  xbuf[(size_t)tp*256 + 192 + col]));
            HsP[(size_t)tp * HSP_STRIDE + col] = d_add2(s, d_dup(bias[col]));
        }
    }

    // ---- GEMM2 + softmax + routing per slice ----
    do_slice<N_QK, 0>(sm, tid);
    do_slice<N_V,  N_QK>(sm, tid);
    do_slice<N_REL, N_QK + N_V>(sm, tid);
    do_slice<N_VAL, N_QK + N_V + N_REL>(sm, tid);

    __syncthreads();
    for (int i = tid; i < N_TOT; i += NTHREADS)
        g_wpart[blockIdx.x][i] = w_local[i];

    // ---- completion counter: last block of this batch finalizes ----
    int* lastFlag = (int*)(sm + SM_FLAGW);
    __threadfence();
    if (tid == 0) {
        int old = atomicAdd(&g_cnt[bb], 1);
        *lastFlag = (old == 15);
    }
    __syncthreads();
    if (!*lastFlag) return;

    // finalize: deterministic sum of the 16 partials, then top-k tasks
    float* sws  = (float*)sm;                 // [928]
    int*   flag = (int*)(sm + 4096);          // [512]
    for (int n = tid; n < N_TOT; n += NTHREADS) {
        float s = 0.0f;
        #pragma unroll
        for (int l = 0; l < 16; l++) s += g_wpart[bb * 16 + l][n];
        sws[n] = s;
    }
    __syncthreads();

    // raw w copies
    for (int i = tid; i < N_QK; i += NTHREADS) out[OFF_WQK + bb * N_QK + i] = sws[i];
    for (int i = tid; i < N_V;  i += NTHREADS) out[OFF_WV  + bb * N_V  + i] = sws[N_QK + i];

    // task 1: qk top-64 indices
    topk_flags<N_QK, K_QK>(sws, flag, tid);
    __syncthreads();
    for (int i = tid; i < N_QK; i += NTHREADS) {
        if (flag[i]) {
            int pos = 0;
            for (int j = 0; j < i; j++) pos += flag[j];
            out[OFF_IDXQK + bb * K_QK + pos] = (float)i;
        }
    }
    __syncthreads();
    // task 2: v top-32 indices
    topk_flags<N_V, K_V>(sws + N_QK, flag, tid);
    __syncthreads();
    for (int i = tid; i < N_V; i += NTHREADS) {
        if (flag[i]) {
            int pos = 0;
            for (int j = 0; j < i; j++) pos += flag[j];
            out[OFF_IDXV + bb * K_V + pos] = (float)i;
        }
    }
    __syncthreads();
    // task 3: rel sparsify top-16 (rw_Q == rw_K)
    topk_flags<N_REL, K_REL>(sws + N_QK + N_V, flag, tid);
    __syncthreads();
    for (int i = tid; i < N_REL; i += NTHREADS) {
        float v = flag[i] ? sws[N_QK + N_V + i] : 0.0f;
        out[OFF_RWQ + bb * N_REL + i] = v;
        out[OFF_RWK + bb * N_REL + i] = v;
    }
    __syncthreads();
    // task 4: val sparsify top-3
    topk_flags<N_VAL, K_VAL>(sws + N_QK + N_V + N_REL, flag, tid);
    __syncthreads();
    for (int i = tid; i < N_VAL; i += NTHREADS)
        out[OFF_VW + bb * N_VAL + i] = flag[i] ? sws[N_QK + N_V + N_REL + i] : 0.0f;
}

extern "C" void kernel_launch(void* const* d_in, const int* in_sizes, int n_in,
                              void* d_out, int out_size) {
    const float* x    = (const float*)d_in[0];
    const float* imp  = (const float*)d_in[1];
    const float* Wm   = (const float*)d_in[2];
    const float* bias = (const float*)d_in[3];
    const float* emb  = (const float*)d_in[4];
    float* out = (float*)d_out;

    cudaFuncSetAttribute(main_kernel, cudaFuncAttributeMaxDynamicSharedMemorySize, SMEM_BYTES);

    prep_kernel<<<N_TOT, 64>>>(emb);
    main_kernel<<<NBLOCKS, NTHREADS, SMEM_BYTES>>>(x, imp, Wm, bias, out);
}